// round 10
// baseline (speedup 1.0000x reference)
#include <cuda_runtime.h>
#include <cstdint>
#include <math.h>

#define T_SEQ 512
#define B_    64
#define H_    1024
#define G_    3072
#define L_    3
#define NBLK  128
#define CLS   4          // cluster size = K-splits
#define GPB   96         // local gate columns per cluster-group (32 units x 3 gates)
#define KPB   256        // K elements per rank

// dynamic SMEM layout for recur (in 4-byte words):
//   Ws[96][260] tf32, hs[64][260] tf32, part_s[64][100] float
#define WS_W   260
#define HS_OFF (96 * WS_W)
#define PT_OFF (HS_OFF + 64 * WS_W)
#define PT_W   100
#define SMEMB  ((PT_OFF + 64 * PT_W) * 4)   // 192000 B

__device__ float g_gx[(size_t)T_SEQ * B_ * G_];
__device__ float g_seqA[(size_t)T_SEQ * B_ * H_];
__device__ float g_seqB[(size_t)T_SEQ * B_ * H_];
__device__ float g_hbuf[3][B_ * H_];          // triple buffer: read t%3, write (t+1)%3
__device__ unsigned g_cnt[32];                // per-group step-completion counters

__device__ __forceinline__ unsigned f2tf(float x) {
    unsigned u;
    asm("cvt.rna.tf32.f32 %0, %1;" : "=r"(u) : "f"(x));
    return u;
}

__device__ __forceinline__ void mma_tf32(float* c, const unsigned* a, const unsigned* b) {
    asm volatile(
        "mma.sync.aligned.m16n8k8.row.col.f32.tf32.tf32.f32 "
        "{%0,%1,%2,%3}, {%4,%5,%6,%7}, {%8,%9}, {%0,%1,%2,%3};"
        : "+f"(c[0]), "+f"(c[1]), "+f"(c[2]), "+f"(c[3])
        : "r"(a[0]), "r"(a[1]), "r"(a[2]), "r"(a[3]), "r"(b[0]), "r"(b[1]));
}

__global__ void reset_cnt() { if (threadIdx.x < 32) g_cnt[threadIdx.x] = 0u; }

__device__ __forceinline__ uint32_t s2u(const void* p) {
    uint32_t a;
    asm("{ .reg .u64 t; cvta.to.shared.u64 t, %1; cvt.u32.u64 %0, t; }" : "=r"(a) : "l"(p));
    return a;
}

// DSMEM scalar read from cluster rank r at the same SMEM offset
__device__ __forceinline__ float dsmem_ld(uint32_t laddr, uint32_t rank) {
    uint32_t ra; float v;
    asm("mapa.shared::cluster.u32 %0, %1, %2;" : "=r"(ra) : "r"(laddr), "r"(rank));
    asm volatile("ld.shared::cluster.f32 %0, [%1];" : "=f"(v) : "r"(ra) : "memory");
    return v;
}

// ---------------- input-gate GEMM (unchanged, proven ~2us/launch) ----------------
__global__ void __launch_bounds__(256, 2) gx_gemm(
    const float* __restrict__ Aext, int sel,
    const float* __restrict__ W, const float* __restrict__ bias)
{
    const float* A = (sel == 0) ? Aext : (sel == 1 ? g_seqA : g_seqB);
    float* out = g_gx;

    __shared__ unsigned As[16][136];
    __shared__ unsigned Bs[16][136];

    const int tid = threadIdx.x;
    const int mbase = blockIdx.y * 128, nbase = blockIdx.x * 128;
    const int lane = tid & 31, warp = tid >> 5;
    const int wm = (warp >> 2) * 64;
    const int wn = (warp & 3) * 32;
    const int q = lane & 3, g8 = lane >> 2;

    float acc[4][4][4];
#pragma unroll
    for (int i = 0; i < 4; i++)
#pragma unroll
        for (int j = 0; j < 4; j++)
#pragma unroll
            for (int k = 0; k < 4; k++) acc[i][j][k] = 0.f;

    for (int kt = 0; kt < H_; kt += 16) {
        __syncthreads();
#pragma unroll
        for (int r = 0; r < 2; r++) {
            int id = tid + r * 256;
            int row = id >> 2;
            int kc = (id & 3) << 2;
            float4 va = *(const float4*)(A + (size_t)(mbase + row) * H_ + kt + kc);
            As[kc + 0][row] = f2tf(va.x); As[kc + 1][row] = f2tf(va.y);
            As[kc + 2][row] = f2tf(va.z); As[kc + 3][row] = f2tf(va.w);
            float4 vb = *(const float4*)(W + (size_t)(nbase + row) * H_ + kt + kc);
            Bs[kc + 0][row] = f2tf(vb.x); Bs[kc + 1][row] = f2tf(vb.y);
            Bs[kc + 2][row] = f2tf(vb.z); Bs[kc + 3][row] = f2tf(vb.w);
        }
        __syncthreads();
#pragma unroll
        for (int ks = 0; ks < 16; ks += 8) {
            unsigned a[4][4], b[4][2];
#pragma unroll
            for (int mi = 0; mi < 4; mi++) {
                int m0 = wm + mi * 16 + g8;
                a[mi][0] = As[ks + q][m0];
                a[mi][1] = As[ks + q][m0 + 8];
                a[mi][2] = As[ks + 4 + q][m0];
                a[mi][3] = As[ks + 4 + q][m0 + 8];
            }
#pragma unroll
            for (int ni = 0; ni < 4; ni++) {
                int n0 = wn + ni * 8 + g8;
                b[ni][0] = Bs[ks + q][n0];
                b[ni][1] = Bs[ks + 4 + q][n0];
            }
#pragma unroll
            for (int mi = 0; mi < 4; mi++)
#pragma unroll
                for (int ni = 0; ni < 4; ni++)
                    mma_tf32(acc[mi][ni], a[mi], b[ni]);
        }
    }
#pragma unroll
    for (int mi = 0; mi < 4; mi++) {
        int m = mbase + wm + mi * 16 + g8;
#pragma unroll
        for (int ni = 0; ni < 4; ni++) {
            int n = nbase + wn + ni * 8 + 2 * q;
            float b0 = bias[n], b1 = bias[n + 1];
            *(float2*)(out + (size_t)m * G_ + n) =
                make_float2(acc[mi][ni][0] + b0, acc[mi][ni][1] + b1);
            *(float2*)(out + (size_t)(m + 8) * G_ + n) =
                make_float2(acc[mi][ni][2] + b0, acc[mi][ni][3] + b1);
        }
    }
}

// ---------------- persistent recurrence: dataflow sync, no global barrier ----------------
extern __shared__ unsigned sh[];

__global__ void __launch_bounds__(256) __cluster_dims__(CLS, 1, 1) recur(
    const float* __restrict__ Whh, const float* __restrict__ bhh,
    const float* __restrict__ h0, int outsel, float* __restrict__ hlast)
{
    unsigned (*Ws)[WS_W] = (unsigned(*)[WS_W])sh;
    unsigned (*hs)[WS_W] = (unsigned(*)[WS_W])(sh + HS_OFF);
    float    (*ps)[PT_W] = (float(*)[PT_W])(sh + PT_OFF);
    float* seqout = outsel ? g_seqB : g_seqA;

    const int tid = threadIdx.x, blk = blockIdx.x;
    const int grp = blk >> 2;          // 0..31 : which 32-hidden-unit group
    const uint32_t rank = blk & 3;     // 0..3  : K-split rank == cluster ctarank
    const int lane = tid & 31, warp = tid >> 5;
    const int q = lane & 3, g8 = lane >> 2;
    const int wm = (warp >> 1) * 16;   // 4 warps in M (64)
    const int wn = (warp & 1) * 48;    // 2 warps in N (96)

    const uint32_t ps_base = s2u(&ps[0][0]);

    // stage W_hh slice -> SMEM tf32, once per layer.
    // local col r = gate*32 + unit  ->  W row = gate*1024 + grp*32 + unit
#pragma unroll
    for (int it = 0; it < 24; it++) {
        int id = tid + it * 256;       // 96 rows x 64 quads
        int r = id >> 6, k = (id & 63) * 4;
        int wrow = (r >> 5) * H_ + grp * 32 + (r & 31);
        float4 v = *(const float4*)(Whh + (size_t)wrow * H_ + rank * KPB + k);
        *(uint4*)&Ws[r][k] = make_uint4(f2tf(v.x), f2tf(v.y), f2tf(v.z), f2tf(v.w));
    }

    for (int t = 0; t < T_SEQ; t++) {
        // ---- dataflow wait: my 8 producer groups finished step t-1 ----
        if (t > 0) {
            if (warp == 0 && lane < 8) {
                const unsigned tgt = 4u * (unsigned)t;
                const unsigned* cp = &g_cnt[rank * 8 + lane];
                unsigned v;
                do {
                    asm volatile("ld.acquire.gpu.u32 %0, [%1];" : "=r"(v) : "l"(cp) : "memory");
                } while (v < tgt);
            }
            __syncthreads();
        }

        const float* hsrc = (t == 0) ? h0 : g_hbuf[t % 3];

        // ---- stage h slice [64 x 256] ----
#pragma unroll
        for (int it = 0; it < 16; it++) {
            int id = tid + it * 256;   // 64 rows x 64 quads
            int r = id >> 6, k = (id & 63) * 4;
            float4 v = __ldcg((const float4*)(hsrc + (size_t)r * H_ + rank * KPB + k));
            *(uint4*)&hs[r][k] = make_uint4(f2tf(v.x), f2tf(v.y), f2tf(v.z), f2tf(v.w));
        }
        __syncthreads();

        // ---- GEMM 64x96x256 (proven tiling) ----
        float acc[6][4];
#pragma unroll
        for (int ni = 0; ni < 6; ni++)
#pragma unroll
            for (int k = 0; k < 4; k++) acc[ni][k] = 0.f;

#pragma unroll 4
        for (int kt = 0; kt < KPB; kt += 8) {
            unsigned a[4];
            a[0] = hs[wm + g8][kt + q];
            a[1] = hs[wm + g8 + 8][kt + q];
            a[2] = hs[wm + g8][kt + q + 4];
            a[3] = hs[wm + g8 + 8][kt + q + 4];
#pragma unroll
            for (int ni = 0; ni < 6; ni++) {
                unsigned b[2];
                b[0] = Ws[wn + ni * 8 + g8][kt + q];
                b[1] = Ws[wn + ni * 8 + g8][kt + q + 4];
                mma_tf32(acc[ni], a, b);
            }
        }

        // W2: peers' DSMEM reads of previous step's ps are done (pairs with A2 of t-1)
        if (t > 0)
            asm volatile("barrier.cluster.wait.aligned;" ::: "memory");

        // epilogue -> local SMEM partial tile [64][96]
#pragma unroll
        for (int ni = 0; ni < 6; ni++) {
            int n = wn + ni * 8 + 2 * q;
            int m0 = wm + g8;
            ps[m0][n] = acc[ni][0];     ps[m0][n + 1] = acc[ni][1];
            ps[m0 + 8][n] = acc[ni][2]; ps[m0 + 8][n + 1] = acc[ni][3];
        }
        __syncthreads();

        // A1 + W1: all 4 ranks' ps visible
        asm volatile("barrier.cluster.arrive.aligned;" ::: "memory");
        asm volatile("barrier.cluster.wait.aligned;" ::: "memory");

        // ---- fused reduction + gates for this rank's 8 hidden units ----
        {
            float* hwr = g_hbuf[(t + 1) % 3];
#pragma unroll
            for (int o = 0; o < 2; o++) {
                int oi = tid + o * 256;          // 0..511
                int b = oi >> 3;                 // batch 0..63
                int ucol = (int)rank * 8 + (oi & 7);
                int ghid = grp * 32 + ucol;      // global hidden unit

                float sr = 0.f, sz = 0.f, sn = 0.f;
#pragma unroll
                for (uint32_t r = 0; r < CLS; r++) {
                    uint32_t a0 = ps_base + (uint32_t)(b * PT_W + ucol) * 4u;
                    sr += dsmem_ld(a0, r);
                    sz += dsmem_ld(a0 + 32 * 4, r);
                    sn += dsmem_ld(a0 + 64 * 4, r);
                }

                const float* gxt = g_gx + ((size_t)t * B_ + b) * G_;
                float xr = __ldcg(gxt + ghid);
                float xz = __ldcg(gxt + H_ + ghid);
                float xn = __ldcg(gxt + 2 * H_ + ghid);
                float br = bhh[ghid], bz = bhh[H_ + ghid], bn = bhh[2 * H_ + ghid];
                float hold = (t == 0) ? h0[(size_t)b * H_ + ghid]
                                      : __ldcg(&g_hbuf[t % 3][(size_t)b * H_ + ghid]);

                float rr = 1.f / (1.f + expf(-(xr + sr + br)));
                float zz = 1.f / (1.f + expf(-(xz + sz + bz)));
                float nn = tanhf(xn + rr * (sn + bn));
                float hv = (1.f - zz) * nn + zz * hold;

                hwr[(size_t)b * H_ + ghid] = hv;
                seqout[((size_t)t * B_ + b) * H_ + ghid] = hv;
                if (t == T_SEQ - 1)
                    hlast[(size_t)b * H_ + ghid] = hv;
            }
        }

        // A2: my DSMEM reads done (matched by W2 of t+1)
        asm volatile("barrier.cluster.arrive.aligned;" ::: "memory");

        // publish: all my h writes for step t are visible -> bump my group's counter
        __syncthreads();
        if (tid == 0)
            asm volatile("red.release.gpu.add.u32 [%0], %1;"
                         :: "l"(&g_cnt[grp]), "r"(1u) : "memory");
    }

    // balance the trailing A2
    asm volatile("barrier.cluster.wait.aligned;" ::: "memory");
}

extern "C" void kernel_launch(void* const* d_in, const int* in_sizes, int n_in,
                              void* d_out, int out_size)
{
    const float* x   = (const float*)d_in[0];
    const float* h0  = (const float*)d_in[1];
    const float* Wih = (const float*)d_in[2];
    const float* Whh = (const float*)d_in[3];
    const float* bih = (const float*)d_in[4];
    const float* bhh = (const float*)d_in[5];
    float* out = (float*)d_out;

    cudaFuncSetAttribute(recur, cudaFuncAttributeMaxDynamicSharedMemorySize, SMEMB);

    dim3 ggrid(G_ / 128, (T_SEQ * B_) / 128);
    for (int l = 0; l < L_; l++) {
        const float* a_ext = (l == 0) ? x : nullptr;
        gx_gemm<<<ggrid, 256>>>(a_ext, l == 0 ? 0 : (l == 1 ? 1 : 2),
                                Wih + (size_t)l * G_ * H_, bih + (size_t)l * G_);
        reset_cnt<<<1, 32>>>();
        recur<<<NBLK, 256, SMEMB>>>(Whh + (size_t)l * G_ * H_,
                                    bhh + (size_t)l * G_,
                                    h0 + (size_t)l * B_ * H_,
                                    l & 1 ? 1 : 0,
                                    out + (size_t)l * B_ * H_);
    }
}

// round 12
// speedup vs baseline: 1.0202x; 1.0202x over previous
#include <cuda_runtime.h>
#include <cstdint>
#include <math.h>

#define T_SEQ 512
#define B_    64
#define H_    1024
#define G_    3072
#define L_    3
#define NBLK  128
#define CLS   4          // cluster size = K-splits (proven resident)
#define NGRP  32         // hidden-unit groups (32 units each)
#define KPB   256        // K elements per rank

// recur dynamic SMEM (words): hs[64][260] tf32, ps[64][100] float
#define HS_W   260
#define PT_OFF (64 * HS_W)
#define PT_W   100
#define SMEMB  ((PT_OFF + 64 * PT_W) * 4)   // 92160 B

__device__ float g_gx[(size_t)T_SEQ * B_ * G_];
__device__ float g_seqA[(size_t)T_SEQ * B_ * H_];
__device__ float g_seqB[(size_t)T_SEQ * B_ * H_];
__device__ float g_hbuf[3][B_ * H_];          // triple buffer: read t%3, write (t+1)%3
__device__ unsigned g_cnt[NGRP];              // per-group step counters (+4 per step)

__device__ __forceinline__ unsigned f2tf(float x) {
    unsigned u;
    asm("cvt.rna.tf32.f32 %0, %1;" : "=r"(u) : "f"(x));
    return u;
}

__device__ __forceinline__ void mma_tf32(float* c, const unsigned* a, const unsigned* b) {
    asm volatile(
        "mma.sync.aligned.m16n8k8.row.col.f32.tf32.tf32.f32 "
        "{%0,%1,%2,%3}, {%4,%5,%6,%7}, {%8,%9}, {%0,%1,%2,%3};"
        : "+f"(c[0]), "+f"(c[1]), "+f"(c[2]), "+f"(c[3])
        : "r"(a[0]), "r"(a[1]), "r"(a[2]), "r"(a[3]), "r"(b[0]), "r"(b[1]));
}

__global__ void reset_cnt() { if (threadIdx.x < NGRP) g_cnt[threadIdx.x] = 0u; }

__device__ __forceinline__ uint32_t s2u(const void* p) {
    uint32_t a;
    asm("{ .reg .u64 t; cvta.to.shared.u64 t, %1; cvt.u32.u64 %0, t; }" : "=r"(a) : "l"(p));
    return a;
}

__device__ __forceinline__ float dsmem_ld(uint32_t laddr, uint32_t rank) {
    uint32_t ra; float v;
    asm("mapa.shared::cluster.u32 %0, %1, %2;" : "=r"(ra) : "r"(laddr), "r"(rank));
    asm volatile("ld.shared::cluster.f32 %0, [%1];" : "=f"(v) : "r"(ra) : "memory");
    return v;
}

// ---------------- input-gate GEMM: block 128Mx256N, warp tile 64x64 ----------------
__global__ void __launch_bounds__(256, 1) gx_gemm(
    const float* __restrict__ Aext, int sel,
    const float* __restrict__ W, const float* __restrict__ bias)
{
    const float* A = (sel == 0) ? Aext : (sel == 1 ? g_seqA : g_seqB);
    float* out = g_gx;

    __shared__ unsigned As[16][136];
    __shared__ unsigned Bs[16][264];

    const int tid = threadIdx.x;
    const int mbase = blockIdx.y * 128, nbase = blockIdx.x * 256;
    const int lane = tid & 31, warp = tid >> 5;
    const int wm = (warp >> 2) * 64;   // 2 warps in M
    const int wn = (warp & 3) * 64;    // 4 warps in N
    const int q = lane & 3, g8 = lane >> 2;

    float acc[4][8][4];
#pragma unroll
    for (int i = 0; i < 4; i++)
#pragma unroll
        for (int j = 0; j < 8; j++)
#pragma unroll
            for (int k = 0; k < 4; k++) acc[i][j][k] = 0.f;

    for (int kt = 0; kt < H_; kt += 16) {
        __syncthreads();
#pragma unroll
        for (int r = 0; r < 2; r++) {
            int id = tid + r * 256;
            int row = id >> 2;
            int kc = (id & 3) << 2;
            float4 va = *(const float4*)(A + (size_t)(mbase + row) * H_ + kt + kc);
            As[kc + 0][row] = f2tf(va.x); As[kc + 1][row] = f2tf(va.y);
            As[kc + 2][row] = f2tf(va.z); As[kc + 3][row] = f2tf(va.w);
        }
#pragma unroll
        for (int r = 0; r < 4; r++) {
            int id = tid + r * 256;
            int row = id >> 2;
            int kc = (id & 3) << 2;
            float4 vb = *(const float4*)(W + (size_t)(nbase + row) * H_ + kt + kc);
            Bs[kc + 0][row] = f2tf(vb.x); Bs[kc + 1][row] = f2tf(vb.y);
            Bs[kc + 2][row] = f2tf(vb.z); Bs[kc + 3][row] = f2tf(vb.w);
        }
        __syncthreads();
#pragma unroll
        for (int ks = 0; ks < 16; ks += 8) {
            unsigned a[4][4], b[8][2];
#pragma unroll
            for (int mi = 0; mi < 4; mi++) {
                int m0 = wm + mi * 16 + g8;
                a[mi][0] = As[ks + q][m0];
                a[mi][1] = As[ks + q][m0 + 8];
                a[mi][2] = As[ks + 4 + q][m0];
                a[mi][3] = As[ks + 4 + q][m0 + 8];
            }
#pragma unroll
            for (int ni = 0; ni < 8; ni++) {
                int n0 = wn + ni * 8 + g8;
                b[ni][0] = Bs[ks + q][n0];
                b[ni][1] = Bs[ks + 4 + q][n0];
            }
#pragma unroll
            for (int mi = 0; mi < 4; mi++)
#pragma unroll
                for (int ni = 0; ni < 8; ni++)
                    mma_tf32(acc[mi][ni], a[mi], b[ni]);
        }
    }
#pragma unroll
    for (int mi = 0; mi < 4; mi++) {
        int m = mbase + wm + mi * 16 + g8;
#pragma unroll
        for (int ni = 0; ni < 8; ni++) {
            int n = nbase + wn + ni * 8 + 2 * q;
            float b0 = bias[n], b1 = bias[n + 1];
            *(float2*)(out + (size_t)m * G_ + n) =
                make_float2(acc[mi][ni][0] + b0, acc[mi][ni][1] + b1);
            *(float2*)(out + (size_t)(m + 8) * G_ + n) =
                make_float2(acc[mi][ni][2] + b0, acc[mi][ni][3] + b1);
        }
    }
}

// ---------------- persistent recurrence: 32 clusters of 4, W_hh register-resident ----------------
extern __shared__ unsigned sh[];

__global__ void __launch_bounds__(256, 1) __cluster_dims__(CLS, 1, 1) recur(
    const float* __restrict__ Whh, const float* __restrict__ bhh,
    const float* __restrict__ h0, int outsel, float* __restrict__ hlast)
{
    unsigned (*hs)[HS_W] = (unsigned(*)[HS_W])sh;
    float    (*ps)[PT_W] = (float(*)[PT_W])(sh + PT_OFF);
    float* seqout = outsel ? g_seqB : g_seqA;

    const int tid = threadIdx.x, blk = blockIdx.x;
    const int grp = blk >> 2;          // 0..31 : 32-hidden-unit group
    const uint32_t rank = blk & 3;     // 0..3  : K-split rank == cluster ctarank
    const int lane = tid & 31, warp = tid >> 5;
    const int q = lane & 3, g8 = lane >> 2;
    const int wq = warp & 3;           // column quarter: 24 local cols
    const int kh = warp >> 2;          // K half: 128 elements

    const uint32_t ps_base = s2u(&ps[0][0]);

    // ---- load W_hh fragments into registers, once per layer ----
    // local col n = gate*32 + unit ; this warp: cols [24*wq, 24*wq+24), K [128*kh, 128*kh+128)
    unsigned wreg[16][3][2];
#pragma unroll
    for (int kc = 0; kc < 16; kc++)
#pragma unroll
        for (int ni = 0; ni < 3; ni++) {
            int col = wq * 24 + ni * 8 + g8;
            int wrow = (col >> 5) * H_ + grp * 32 + (col & 31);
            size_t base = (size_t)wrow * H_ + rank * KPB + kh * 128 + kc * 8 + q;
            wreg[kc][ni][0] = f2tf(Whh[base]);
            wreg[kc][ni][1] = f2tf(Whh[base + 4]);
        }

    for (int t = 0; t < T_SEQ; t++) {
        // ---- dataflow wait: my 8 producer groups finished step t-1 ----
        if (t > 0) {
            if (warp == 0 && lane < 8) {
                const unsigned tgt = 4u * (unsigned)t;
                const unsigned* cp = &g_cnt[rank * 8 + lane];
                unsigned v;
                do {
                    asm volatile("ld.acquire.gpu.u32 %0, [%1];" : "=r"(v) : "l"(cp) : "memory");
                } while (v < tgt);
            }
            __syncthreads();
        }

        const float* hsrc = (t == 0) ? h0 : g_hbuf[t % 3];

        // ---- stage h slice [64 x 256] -> tf32 SMEM ----
#pragma unroll
        for (int it = 0; it < 16; it++) {
            int id = tid + it * 256;   // 64 rows x 64 quads
            int r = id >> 6, c4 = id & 63;
            float4 v = __ldcg((const float4*)(hsrc + (size_t)r * H_ + rank * KPB + c4 * 4));
            *(uint4*)&hs[r][c4 * 4] = make_uint4(f2tf(v.x), f2tf(v.y), f2tf(v.z), f2tf(v.w));
        }
        __syncthreads();

        // ---- GEMM: each warp 64Mx24Nx128K, B from registers ----
        float acc[4][3][4];
#pragma unroll
        for (int mi = 0; mi < 4; mi++)
#pragma unroll
            for (int ni = 0; ni < 3; ni++)
#pragma unroll
                for (int k = 0; k < 4; k++) acc[mi][ni][k] = 0.f;

#pragma unroll
        for (int kc = 0; kc < 16; kc++) {
            int kb = kh * 128 + kc * 8;
            unsigned a[4][4];
#pragma unroll
            for (int mi = 0; mi < 4; mi++) {
                int m0 = mi * 16 + g8;
                a[mi][0] = hs[m0][kb + q];
                a[mi][1] = hs[m0 + 8][kb + q];
                a[mi][2] = hs[m0][kb + q + 4];
                a[mi][3] = hs[m0 + 8][kb + q + 4];
            }
#pragma unroll
            for (int mi = 0; mi < 4; mi++)
#pragma unroll
                for (int ni = 0; ni < 3; ni++)
                    mma_tf32(acc[mi][ni], a[mi], wreg[kc][ni]);
        }

        // W2: peers' DSMEM reads of previous step's ps are done (pairs with A2 of t-1)
        if (t > 0)
            asm volatile("barrier.cluster.wait.aligned;" ::: "memory");

        // epilogue: K-hi warps store ps, then K-lo warps accumulate
        if (kh == 1) {
#pragma unroll
            for (int mi = 0; mi < 4; mi++)
#pragma unroll
                for (int ni = 0; ni < 3; ni++) {
                    int n = wq * 24 + ni * 8 + 2 * q;
                    int m0 = mi * 16 + g8;
                    ps[m0][n] = acc[mi][ni][0];     ps[m0][n + 1] = acc[mi][ni][1];
                    ps[m0 + 8][n] = acc[mi][ni][2]; ps[m0 + 8][n + 1] = acc[mi][ni][3];
                }
        }
        __syncthreads();
        if (kh == 0) {
#pragma unroll
            for (int mi = 0; mi < 4; mi++)
#pragma unroll
                for (int ni = 0; ni < 3; ni++) {
                    int n = wq * 24 + ni * 8 + 2 * q;
                    int m0 = mi * 16 + g8;
                    ps[m0][n] += acc[mi][ni][0];     ps[m0][n + 1] += acc[mi][ni][1];
                    ps[m0 + 8][n] += acc[mi][ni][2]; ps[m0 + 8][n + 1] += acc[mi][ni][3];
                }
        }
        __syncthreads();

        // A1 + W1: all 4 ranks' ps visible
        asm volatile("barrier.cluster.arrive.aligned;" ::: "memory");
        asm volatile("barrier.cluster.wait.aligned;" ::: "memory");

        // ---- fused reduction + gates for this rank's 8 hidden units ----
        {
            float* hwr = g_hbuf[(t + 1) % 3];
#pragma unroll
            for (int o = 0; o < 2; o++) {
                int oi = tid + o * 256;          // 0..511
                int b = oi >> 3;                 // batch 0..63
                int ucol = (int)rank * 8 + (oi & 7);
                int ghid = grp * 32 + ucol;      // global hidden unit

                float sr = 0.f, sz = 0.f, sn = 0.f;
#pragma unroll
                for (uint32_t r = 0; r < CLS; r++) {
                    uint32_t a0 = ps_base + (uint32_t)(b * PT_W + ucol) * 4u;
                    sr += dsmem_ld(a0, r);
                    sz += dsmem_ld(a0 + 32 * 4, r);
                    sn += dsmem_ld(a0 + 64 * 4, r);
                }

                const float* gxt = g_gx + ((size_t)t * B_ + b) * G_;
                float xr = __ldcg(gxt + ghid);
                float xz = __ldcg(gxt + H_ + ghid);
                float xn = __ldcg(gxt + 2 * H_ + ghid);
                float br = bhh[ghid], bz = bhh[H_ + ghid], bn = bhh[2 * H_ + ghid];
                float hold = (t == 0) ? h0[(size_t)b * H_ + ghid]
                                      : __ldcg(&g_hbuf[t % 3][(size_t)b * H_ + ghid]);

                float rr = 1.f / (1.f + expf(-(xr + sr + br)));
                float zz = 1.f / (1.f + expf(-(xz + sz + bz)));
                float nn = tanhf(xn + rr * (sn + bn));
                float hv = (1.f - zz) * nn + zz * hold;

                hwr[(size_t)b * H_ + ghid] = hv;
                seqout[((size_t)t * B_ + b) * H_ + ghid] = hv;
                if (t == T_SEQ - 1)
                    hlast[(size_t)b * H_ + ghid] = hv;
            }
        }

        // A2: my DSMEM reads done (matched by W2 of t+1)
        asm volatile("barrier.cluster.arrive.aligned;" ::: "memory");

        // publish: all my h writes for step t visible -> bump my group's counter
        __syncthreads();
        if (tid == 0)
            asm volatile("red.release.gpu.add.u32 [%0], %1;"
                         :: "l"(&g_cnt[grp]), "r"(1u) : "memory");
    }

    // balance the trailing A2
    asm volatile("barrier.cluster.wait.aligned;" ::: "memory");
}

extern "C" void kernel_launch(void* const* d_in, const int* in_sizes, int n_in,
                              void* d_out, int out_size)
{
    const float* x   = (const float*)d_in[0];
    const float* h0  = (const float*)d_in[1];
    const float* Wih = (const float*)d_in[2];
    const float* Whh = (const float*)d_in[3];
    const float* bih = (const float*)d_in[4];
    const float* bhh = (const float*)d_in[5];
    float* out = (float*)d_out;

    cudaFuncSetAttribute(recur, cudaFuncAttributeMaxDynamicSharedMemorySize, SMEMB);

    dim3 ggrid(G_ / 256, (T_SEQ * B_) / 128);
    for (int l = 0; l < L_; l++) {
        const float* a_ext = (l == 0) ? x : nullptr;
        gx_gemm<<<ggrid, 256>>>(a_ext, l == 0 ? 0 : (l == 1 ? 1 : 2),
                                Wih + (size_t)l * G_ * H_, bih + (size_t)l * G_);
        reset_cnt<<<1, 32>>>();
        recur<<<NBLK, 256, SMEMB>>>(Whh + (size_t)l * G_ * H_,
                                    bhh + (size_t)l * G_,
                                    h0 + (size_t)l * B_ * H_,
                                    l & 1 ? 1 : 0,
                                    out + (size_t)l * B_ * H_);
    }
}

// round 13
// speedup vs baseline: 1.2585x; 1.2335x over previous
#include <cuda_runtime.h>
#include <cuda_fp16.h>
#include <cstdint>
#include <math.h>

#define T_SEQ 512
#define B_    64
#define H_    1024
#define G_    3072
#define L_    3
#define NBLK  128
#define CLS   4          // cluster size = K-splits (proven resident)
#define NGRP  32         // hidden-unit groups (32 units each)
#define KPB   256        // K elements per rank

// recur dynamic SMEM (words): hs[64][132] fp16x2 (K=256 -> 128 words), ps[64][100] float
#define HS_W   132
#define PT_OFF (64 * HS_W)
#define PT_W   100
#define SMEMB  ((PT_OFF + 64 * PT_W) * 4)   // 59392 B

__device__ float g_gx[(size_t)T_SEQ * B_ * G_];
__device__ float g_seqA[(size_t)T_SEQ * B_ * H_];
__device__ float g_seqB[(size_t)T_SEQ * B_ * H_];
__device__ float g_hbuf[3][B_ * H_];          // triple buffer: read t%3, write (t+1)%3
__device__ unsigned g_cnt[NGRP];              // per-group step counters (+4 per step)

__device__ __forceinline__ unsigned f2h2(float lo, float hi) {
    __half2 h = __floats2half2_rn(lo, hi);    // .x = lo -> low 16 bits
    return *(unsigned*)&h;
}

__device__ __forceinline__ void mma_f16(float* c, const unsigned* a, const unsigned* b) {
    asm volatile(
        "mma.sync.aligned.m16n8k16.row.col.f32.f16.f16.f32 "
        "{%0,%1,%2,%3}, {%4,%5,%6,%7}, {%8,%9}, {%0,%1,%2,%3};"
        : "+f"(c[0]), "+f"(c[1]), "+f"(c[2]), "+f"(c[3])
        : "r"(a[0]), "r"(a[1]), "r"(a[2]), "r"(a[3]), "r"(b[0]), "r"(b[1]));
}

__global__ void reset_cnt() { if (threadIdx.x < NGRP) g_cnt[threadIdx.x] = 0u; }

__device__ __forceinline__ uint32_t s2u(const void* p) {
    uint32_t a;
    asm("{ .reg .u64 t; cvta.to.shared.u64 t, %1; cvt.u32.u64 %0, t; }" : "=r"(a) : "l"(p));
    return a;
}

__device__ __forceinline__ float dsmem_ld(uint32_t laddr, uint32_t rank) {
    uint32_t ra; float v;
    asm("mapa.shared::cluster.u32 %0, %1, %2;" : "=r"(ra) : "r"(laddr), "r"(rank));
    asm volatile("ld.shared::cluster.f32 %0, [%1];" : "=f"(v) : "r"(ra) : "memory");
    return v;
}

// ---------------- input-gate GEMM: block 128Mx256N, warp 64x64, fp16 MMA ----------------
// SMEM words are fp16x2 pairs along K: As2[k2][m] = pack(A[m][2k2], A[m][2k2+1])
__global__ void __launch_bounds__(256, 1) gx_gemm(
    const float* __restrict__ Aext, int sel,
    const float* __restrict__ W, const float* __restrict__ bias)
{
    const float* A = (sel == 0) ? Aext : (sel == 1 ? g_seqA : g_seqB);
    float* out = g_gx;

    __shared__ unsigned As2[8][136];
    __shared__ unsigned Bs2[8][264];

    const int tid = threadIdx.x;
    const int mbase = blockIdx.y * 128, nbase = blockIdx.x * 256;
    const int lane = tid & 31, warp = tid >> 5;
    const int wm = (warp >> 2) * 64;   // 2 warps in M
    const int wn = (warp & 3) * 64;    // 4 warps in N
    const int q = lane & 3, g8 = lane >> 2;

    float acc[4][8][4];
#pragma unroll
    for (int i = 0; i < 4; i++)
#pragma unroll
        for (int j = 0; j < 8; j++)
#pragma unroll
            for (int k = 0; k < 4; k++) acc[i][j][k] = 0.f;

    for (int kt = 0; kt < H_; kt += 16) {
        __syncthreads();
        // stage A: 128 rows x 16 k  (2 float4 per thread -> 4 packed words)
#pragma unroll
        for (int r = 0; r < 2; r++) {
            int id = tid + r * 256;
            int row = id >> 2;
            int kc = (id & 3) << 2;          // 0,4,8,12
            float4 va = *(const float4*)(A + (size_t)(mbase + row) * H_ + kt + kc);
            As2[(kc >> 1) + 0][row] = f2h2(va.x, va.y);
            As2[(kc >> 1) + 1][row] = f2h2(va.z, va.w);
        }
        // stage B: 256 rows x 16 k
#pragma unroll
        for (int r = 0; r < 4; r++) {
            int id = tid + r * 256;
            int row = id >> 2;
            int kc = (id & 3) << 2;
            float4 vb = *(const float4*)(W + (size_t)(nbase + row) * H_ + kt + kc);
            Bs2[(kc >> 1) + 0][row] = f2h2(vb.x, vb.y);
            Bs2[(kc >> 1) + 1][row] = f2h2(vb.z, vb.w);
        }
        __syncthreads();
        // one m16n8k16 chunk covers the whole 16-k tile
        {
            unsigned a[4][4], b[8][2];
#pragma unroll
            for (int mi = 0; mi < 4; mi++) {
                int m0 = wm + mi * 16 + g8;
                a[mi][0] = As2[q][m0];
                a[mi][1] = As2[q][m0 + 8];
                a[mi][2] = As2[q + 4][m0];
                a[mi][3] = As2[q + 4][m0 + 8];
            }
#pragma unroll
            for (int ni = 0; ni < 8; ni++) {
                int n0 = wn + ni * 8 + g8;
                b[ni][0] = Bs2[q][n0];
                b[ni][1] = Bs2[q + 4][n0];
            }
#pragma unroll
            for (int mi = 0; mi < 4; mi++)
#pragma unroll
                for (int ni = 0; ni < 8; ni++)
                    mma_f16(acc[mi][ni], a[mi], b[ni]);
        }
    }
#pragma unroll
    for (int mi = 0; mi < 4; mi++) {
        int m = mbase + wm + mi * 16 + g8;
#pragma unroll
        for (int ni = 0; ni < 8; ni++) {
            int n = nbase + wn + ni * 8 + 2 * q;
            float b0 = bias[n], b1 = bias[n + 1];
            *(float2*)(out + (size_t)m * G_ + n) =
                make_float2(acc[mi][ni][0] + b0, acc[mi][ni][1] + b1);
            *(float2*)(out + (size_t)(m + 8) * G_ + n) =
                make_float2(acc[mi][ni][2] + b0, acc[mi][ni][3] + b1);
        }
    }
}

// ---------------- persistent recurrence: 32 clusters of 4, fp16 MMA, W in registers ----------------
extern __shared__ unsigned sh[];

__global__ void __launch_bounds__(256, 1) __cluster_dims__(CLS, 1, 1) recur(
    const float* __restrict__ Whh, const float* __restrict__ bhh,
    const float* __restrict__ h0, int outsel, float* __restrict__ hlast)
{
    unsigned (*hs)[HS_W] = (unsigned(*)[HS_W])sh;       // fp16x2 words: hs[row][k/2]
    float    (*ps)[PT_W] = (float(*)[PT_W])(sh + PT_OFF);
    float* seqout = outsel ? g_seqB : g_seqA;

    const int tid = threadIdx.x, blk = blockIdx.x;
    const int grp = blk >> 2;          // 0..31 : 32-hidden-unit group
    const uint32_t rank = blk & 3;     // 0..3  : K-split rank == cluster ctarank
    const int lane = tid & 31, warp = tid >> 5;
    const int q = lane & 3, g8 = lane >> 2;
    const int wq = warp & 3;           // column quarter: 24 local cols
    const int kh = warp >> 2;          // K half: 128 elements = 8 chunks of 16

    const uint32_t ps_base = s2u(&ps[0][0]);

    // ---- load W_hh fragments into registers (fp16x2), once per layer ----
    // local col n = gate*32 + unit ; this warp: cols [24*wq,+24), K [128*kh,+128)
    unsigned wreg[8][3][2];
#pragma unroll
    for (int kc = 0; kc < 8; kc++)
#pragma unroll
        for (int ni = 0; ni < 3; ni++) {
            int col = wq * 24 + ni * 8 + g8;
            int wrow = (col >> 5) * H_ + grp * 32 + (col & 31);
            size_t base = (size_t)wrow * H_ + rank * KPB + kh * 128 + kc * 16;
            wreg[kc][ni][0] = f2h2(Whh[base + 2 * q],     Whh[base + 2 * q + 1]);
            wreg[kc][ni][1] = f2h2(Whh[base + 2 * q + 8], Whh[base + 2 * q + 9]);
        }

    for (int t = 0; t < T_SEQ; t++) {
        // ---- dataflow wait: my 8 producer groups finished step t-1 ----
        if (t > 0) {
            if (warp == 0 && lane < 8) {
                const unsigned tgt = 4u * (unsigned)t;
                const unsigned* cp = &g_cnt[rank * 8 + lane];
                unsigned v;
                do {
                    asm volatile("ld.acquire.gpu.u32 %0, [%1];" : "=r"(v) : "l"(cp) : "memory");
                } while (v < tgt);
            }
            __syncthreads();
        }

        const float* hsrc = (t == 0) ? h0 : g_hbuf[t % 3];

        // ---- stage h slice [64 x 256] -> fp16x2 SMEM (8 uint4 stores/thread) ----
#pragma unroll
        for (int it = 0; it < 8; it++) {
            int id = tid + it * 256;   // 0..2047 = 64 rows x 32 col-octets
            int r = id >> 5, c8 = id & 31;
            const float* src = hsrc + (size_t)r * H_ + rank * KPB + c8 * 8;
            float4 v0 = __ldcg((const float4*)src);
            float4 v1 = __ldcg((const float4*)(src + 4));
            uint4 u = make_uint4(f2h2(v0.x, v0.y), f2h2(v0.z, v0.w),
                                 f2h2(v1.x, v1.y), f2h2(v1.z, v1.w));
            *(uint4*)&hs[r][c8 * 4] = u;
        }
        __syncthreads();

        // ---- GEMM: each warp 64Mx24Nx128K, fp16, B from registers ----
        float acc[4][3][4];
#pragma unroll
        for (int mi = 0; mi < 4; mi++)
#pragma unroll
            for (int ni = 0; ni < 3; ni++)
#pragma unroll
                for (int k = 0; k < 4; k++) acc[mi][ni][k] = 0.f;

#pragma unroll
        for (int kc = 0; kc < 8; kc++) {
            int kb2 = kh * 64 + kc * 8;      // word index of this 16-k chunk
            unsigned a[4][4];
#pragma unroll
            for (int mi = 0; mi < 4; mi++) {
                int m0 = mi * 16 + g8;
                a[mi][0] = hs[m0][kb2 + q];
                a[mi][1] = hs[m0 + 8][kb2 + q];
                a[mi][2] = hs[m0][kb2 + q + 4];
                a[mi][3] = hs[m0 + 8][kb2 + q + 4];
            }
#pragma unroll
            for (int mi = 0; mi < 4; mi++)
#pragma unroll
                for (int ni = 0; ni < 3; ni++)
                    mma_f16(acc[mi][ni], a[mi], wreg[kc][ni]);
        }

        // W2: peers' DSMEM reads of previous step's ps are done (pairs with A2 of t-1)
        if (t > 0)
            asm volatile("barrier.cluster.wait.aligned;" ::: "memory");

        // epilogue: K-hi warps store ps, then K-lo warps accumulate
        if (kh == 1) {
#pragma unroll
            for (int mi = 0; mi < 4; mi++)
#pragma unroll
                for (int ni = 0; ni < 3; ni++) {
                    int n = wq * 24 + ni * 8 + 2 * q;
                    int m0 = mi * 16 + g8;
                    ps[m0][n] = acc[mi][ni][0];     ps[m0][n + 1] = acc[mi][ni][1];
                    ps[m0 + 8][n] = acc[mi][ni][2]; ps[m0 + 8][n + 1] = acc[mi][ni][3];
                }
        }
        __syncthreads();
        if (kh == 0) {
#pragma unroll
            for (int mi = 0; mi < 4; mi++)
#pragma unroll
                for (int ni = 0; ni < 3; ni++) {
                    int n = wq * 24 + ni * 8 + 2 * q;
                    int m0 = mi * 16 + g8;
                    ps[m0][n] += acc[mi][ni][0];     ps[m0][n + 1] += acc[mi][ni][1];
                    ps[m0 + 8][n] += acc[mi][ni][2]; ps[m0 + 8][n + 1] += acc[mi][ni][3];
                }
        }
        __syncthreads();

        // A1 + W1: all 4 ranks' ps visible
        asm volatile("barrier.cluster.arrive.aligned;" ::: "memory");
        asm volatile("barrier.cluster.wait.aligned;" ::: "memory");

        // ---- fused reduction + gates for this rank's 8 hidden units ----
        {
            float* hwr = g_hbuf[(t + 1) % 3];
#pragma unroll
            for (int o = 0; o < 2; o++) {
                int oi = tid + o * 256;          // 0..511
                int b = oi >> 3;                 // batch 0..63
                int ucol = (int)rank * 8 + (oi & 7);
                int ghid = grp * 32 + ucol;      // global hidden unit

                float sr = 0.f, sz = 0.f, sn = 0.f;
#pragma unroll
                for (uint32_t r = 0; r < CLS; r++) {
                    uint32_t a0 = ps_base + (uint32_t)(b * PT_W + ucol) * 4u;
                    sr += dsmem_ld(a0, r);
                    sz += dsmem_ld(a0 + 32 * 4, r);
                    sn += dsmem_ld(a0 + 64 * 4, r);
                }

                const float* gxt = g_gx + ((size_t)t * B_ + b) * G_;
                float xr = __ldcg(gxt + ghid);
                float xz = __ldcg(gxt + H_ + ghid);
                float xn = __ldcg(gxt + 2 * H_ + ghid);
                float br = bhh[ghid], bz = bhh[H_ + ghid], bn = bhh[2 * H_ + ghid];
                float hold = (t == 0) ? h0[(size_t)b * H_ + ghid]
                                      : __ldcg(&g_hbuf[t % 3][(size_t)b * H_ + ghid]);

                float rr = 1.f / (1.f + expf(-(xr + sr + br)));
                float zz = 1.f / (1.f + expf(-(xz + sz + bz)));
                float nn = tanhf(xn + rr * (sn + bn));
                float hv = (1.f - zz) * nn + zz * hold;

                hwr[(size_t)b * H_ + ghid] = hv;
                seqout[((size_t)t * B_ + b) * H_ + ghid] = hv;
                if (t == T_SEQ - 1)
                    hlast[(size_t)b * H_ + ghid] = hv;
            }
        }

        // A2: my DSMEM reads done (matched by W2 of t+1)
        asm volatile("barrier.cluster.arrive.aligned;" ::: "memory");

        // publish: all my h writes for step t visible -> bump my group's counter
        __syncthreads();
        if (tid == 0)
            asm volatile("red.release.gpu.add.u32 [%0], %1;"
                         :: "l"(&g_cnt[grp]), "r"(1u) : "memory");
    }

    // balance the trailing A2
    asm volatile("barrier.cluster.wait.aligned;" ::: "memory");
}

extern "C" void kernel_launch(void* const* d_in, const int* in_sizes, int n_in,
                              void* d_out, int out_size)
{
    const float* x   = (const float*)d_in[0];
    const float* h0  = (const float*)d_in[1];
    const float* Wih = (const float*)d_in[2];
    const float* Whh = (const float*)d_in[3];
    const float* bih = (const float*)d_in[4];
    const float* bhh = (const float*)d_in[5];
    float* out = (float*)d_out;

    cudaFuncSetAttribute(recur, cudaFuncAttributeMaxDynamicSharedMemorySize, SMEMB);

    dim3 ggrid(G_ / 256, (T_SEQ * B_) / 128);
    for (int l = 0; l < L_; l++) {
        const float* a_ext = (l == 0) ? x : nullptr;
        gx_gemm<<<ggrid, 256>>>(a_ext, l == 0 ? 0 : (l == 1 ? 1 : 2),
                                Wih + (size_t)l * G_ * H_, bih + (size_t)l * G_);
        reset_cnt<<<1, 32>>>();
        recur<<<NBLK, 256, SMEMB>>>(Whh + (size_t)l * G_ * H_,
                                    bhh + (size_t)l * G_,
                                    h0 + (size_t)l * B_ * H_,
                                    l & 1 ? 1 : 0,
                                    out + (size_t)l * B_ * H_);
    }
}

// round 14
// speedup vs baseline: 1.5478x; 1.2299x over previous
#include <cuda_runtime.h>
#include <cuda_fp16.h>
#include <cstdint>
#include <math.h>

#define T_SEQ 512
#define B_    64
#define H_    1024
#define G_    3072
#define L_    3
#define NBLK  128
#define CLS   4
#define NGRP  32
#define KPB   256

// recur dynamic SMEM (words): hs[64][132] fp16x2, ps[64][100] float
#define HS_W   132
#define PT_OFF (64 * HS_W)
#define PT_W   100
#define SMEMB_R ((PT_OFF + 64 * PT_W) * 4)   // 59392 B

// gx dynamic SMEM: A stages 2x(128x72) halfs, B stages 2x(128x72) halfs
#define GX_STG   9216                         // halfs per stage tile
#define GX_SMEM  (4 * GX_STG * 2)             // 73728 B
#define GX_NK    16                           // 1024 / 64

__device__ float  g_gx[(size_t)T_SEQ * B_ * G_];
__device__ __half g_xh[(size_t)T_SEQ * B_ * H_];
__device__ __half g_wih[(size_t)L_ * G_ * H_];
__device__ __half g_seqhA[(size_t)T_SEQ * B_ * H_];
__device__ __half g_seqhB[(size_t)T_SEQ * B_ * H_];
__device__ float  g_hbuf[3][B_ * H_];
__device__ unsigned g_cnt[NGRP];

extern __shared__ unsigned sh[];

__device__ __forceinline__ unsigned f2h2(float lo, float hi) {
    __half2 h = __floats2half2_rn(lo, hi);
    return *(unsigned*)&h;
}

__device__ __forceinline__ void mma_f16(float* c, const unsigned* a, const unsigned* b) {
    asm volatile(
        "mma.sync.aligned.m16n8k16.row.col.f32.f16.f16.f32 "
        "{%0,%1,%2,%3}, {%4,%5,%6,%7}, {%8,%9}, {%0,%1,%2,%3};"
        : "+f"(c[0]), "+f"(c[1]), "+f"(c[2]), "+f"(c[3])
        : "r"(a[0]), "r"(a[1]), "r"(a[2]), "r"(a[3]), "r"(b[0]), "r"(b[1]));
}

__device__ __forceinline__ void ldsm4(unsigned* r, uint32_t addr) {
    asm volatile("ldmatrix.sync.aligned.m8n8.x4.shared.b16 {%0,%1,%2,%3}, [%4];"
                 : "=r"(r[0]), "=r"(r[1]), "=r"(r[2]), "=r"(r[3]) : "r"(addr));
}

__device__ __forceinline__ void cpa16(uint32_t dst, const void* src) {
    asm volatile("cp.async.cg.shared.global [%0], [%1], 16;" :: "r"(dst), "l"(src));
}

__global__ void reset_cnt() { if (threadIdx.x < NGRP) g_cnt[threadIdx.x] = 0u; }

// one-shot fp32 -> fp16 conversion (dstsel: 0 = g_xh, 1 = g_wih)
__global__ void tohalf(const float* __restrict__ s, int dstsel, int n8) {
    int i = blockIdx.x * 256 + threadIdx.x;
    if (i >= n8) return;
    __half* d = dstsel ? g_wih : g_xh;
    float4 a = *(const float4*)(s + (size_t)i * 8);
    float4 b = *(const float4*)(s + (size_t)i * 8 + 4);
    uint4 u = make_uint4(f2h2(a.x, a.y), f2h2(a.z, a.w), f2h2(b.x, b.y), f2h2(b.z, b.w));
    *(uint4*)(d + (size_t)i * 8) = u;
}

__device__ __forceinline__ uint32_t s2u(const void* p) {
    uint32_t a;
    asm("{ .reg .u64 t; cvta.to.shared.u64 t, %1; cvt.u32.u64 %0, t; }" : "=r"(a) : "l"(p));
    return a;
}

__device__ __forceinline__ float dsmem_ld(uint32_t laddr, uint32_t rank) {
    uint32_t ra; float v;
    asm("mapa.shared::cluster.u32 %0, %1, %2;" : "=r"(ra) : "r"(laddr), "r"(rank));
    asm volatile("ld.shared::cluster.f32 %0, [%1];" : "=f"(v) : "r"(ra) : "memory");
    return v;
}

// ---------------- input-gate GEMM: fp16 in, cp.async 2-stage, ldmatrix ----------------
// block 128M x 128N x (ktile 64), warp 64x32
__global__ void __launch_bounds__(256, 2) gx_gemm(int sel,
    const __half* __restrict__ Wbase, const float* __restrict__ bias)
{
    const __half* A = (sel == 0) ? g_xh : (sel == 1 ? g_seqhA : g_seqhB);
    const __half* W = Wbase;
    float* out = g_gx;

    const uint32_t smb = s2u(sh);
    const int tid = threadIdx.x, lane = tid & 31, warp = tid >> 5;
    const int mbase = blockIdx.y * 128, nbase = blockIdx.x * 128;
    const int wm = (warp >> 2) * 64;   // 2 warps in M
    const int wn = (warp & 3) * 32;    // 4 warps in N
    const int q = lane & 3, g8 = lane >> 2;

    // ldmatrix per-thread byte offsets within a stage tile (row stride 144 B)
    const int a_off = (wm + (lane & 15)) * 144 + (lane >> 4) * 16;
    const int mm = lane >> 3;
    const int b_off = (wn + (mm >> 1) * 8 + (lane & 7)) * 144 + (mm & 1) * 16;

    // cp.async per-thread chunks: 4 A + 4 B, each 16 B
    int arow[4], aseg[4];
#pragma unroll
    for (int i = 0; i < 4; i++) {
        int id = tid + i * 256;
        arow[i] = id >> 3; aseg[i] = id & 7;
    }

    float acc[4][4][4];
#pragma unroll
    for (int i = 0; i < 4; i++)
#pragma unroll
        for (int j = 0; j < 4; j++)
#pragma unroll
            for (int k = 0; k < 4; k++) acc[i][j][k] = 0.f;

#define GX_STAGE(s, kt)                                                           \
    do {                                                                          \
        _Pragma("unroll")                                                         \
        for (int i = 0; i < 4; i++) {                                             \
            uint32_t dst = smb + ((s) * GX_STG + arow[i] * 72 + aseg[i] * 8) * 2; \
            cpa16(dst, A + (size_t)(mbase + arow[i]) * H_ + (kt) * 64 + aseg[i] * 8); \
        }                                                                         \
        _Pragma("unroll")                                                         \
        for (int i = 0; i < 4; i++) {                                             \
            uint32_t dst = smb + ((2 + (s)) * GX_STG + arow[i] * 72 + aseg[i] * 8) * 2; \
            cpa16(dst, W + (size_t)(nbase + arow[i]) * H_ + (kt) * 64 + aseg[i] * 8);  \
        }                                                                         \
        asm volatile("cp.async.commit_group;" ::: "memory");                      \
    } while (0)

    GX_STAGE(0, 0);

    for (int kt = 0; kt < GX_NK; kt++) {
        if (kt + 1 < GX_NK) {
            GX_STAGE((kt + 1) & 1, kt + 1);
            asm volatile("cp.async.wait_group 1;" ::: "memory");
        } else {
            asm volatile("cp.async.wait_group 0;" ::: "memory");
        }
        __syncthreads();

        const int s = kt & 1;
        const uint32_t abase = smb + s * GX_STG * 2 + a_off;
        const uint32_t bbase = smb + (2 + s) * GX_STG * 2 + b_off;
#pragma unroll
        for (int kc = 0; kc < 4; kc++) {
            unsigned a[4][4], b[2][4];
#pragma unroll
            for (int mi = 0; mi < 4; mi++)
                ldsm4(a[mi], abase + mi * 16 * 144 + kc * 32);
#pragma unroll
            for (int n2 = 0; n2 < 2; n2++)
                ldsm4(b[n2], bbase + n2 * 16 * 144 + kc * 32);
#pragma unroll
            for (int mi = 0; mi < 4; mi++)
#pragma unroll
                for (int ni = 0; ni < 4; ni++)
                    mma_f16(acc[mi][ni], a[mi], &b[ni >> 1][(ni & 1) * 2]);
        }
        __syncthreads();
    }

#pragma unroll
    for (int mi = 0; mi < 4; mi++) {
        int m = mbase + wm + mi * 16 + g8;
#pragma unroll
        for (int ni = 0; ni < 4; ni++) {
            int n = nbase + wn + ni * 8 + 2 * q;
            float b0 = bias[n], b1 = bias[n + 1];
            *(float2*)(out + (size_t)m * G_ + n) =
                make_float2(acc[mi][ni][0] + b0, acc[mi][ni][1] + b1);
            *(float2*)(out + (size_t)(m + 8) * G_ + n) =
                make_float2(acc[mi][ni][2] + b0, acc[mi][ni][3] + b1);
        }
    }
#undef GX_STAGE
}

// ---------------- persistent recurrence: 32 clusters of 4, fp16 MMA, W in registers ----------------
__global__ void __launch_bounds__(256, 1) __cluster_dims__(CLS, 1, 1) recur(
    const float* __restrict__ Whh, const float* __restrict__ bhh,
    const float* __restrict__ h0, int outsel, float* __restrict__ hlast)
{
    unsigned (*hs)[HS_W] = (unsigned(*)[HS_W])sh;
    float    (*ps)[PT_W] = (float(*)[PT_W])(sh + PT_OFF);
    __half* seqh = outsel ? g_seqhB : g_seqhA;

    const int tid = threadIdx.x, blk = blockIdx.x;
    const int grp = blk >> 2;
    const uint32_t rank = blk & 3;
    const int lane = tid & 31, warp = tid >> 5;
    const int q = lane & 3, g8 = lane >> 2;
    const int wq = warp & 3;
    const int kh = warp >> 2;

    const uint32_t ps_base = s2u(&ps[0][0]);

    // per-thread gate indices + loop-invariant biases (hoisted once per layer)
    int b_o[2], ghid_o[2], uc_o[2];
    float br_o[2], bz_o[2], bn_o[2];
#pragma unroll
    for (int o = 0; o < 2; o++) {
        int oi = tid + o * 256;
        b_o[o] = oi >> 3;
        uc_o[o] = (int)rank * 8 + (oi & 7);
        ghid_o[o] = grp * 32 + uc_o[o];
        br_o[o] = bhh[ghid_o[o]];
        bz_o[o] = bhh[H_ + ghid_o[o]];
        bn_o[o] = bhh[2 * H_ + ghid_o[o]];
    }

    // W_hh fragments in registers (fp16x2), once per layer
    unsigned wreg[8][3][2];
#pragma unroll
    for (int kc = 0; kc < 8; kc++)
#pragma unroll
        for (int ni = 0; ni < 3; ni++) {
            int col = wq * 24 + ni * 8 + g8;
            int wrow = (col >> 5) * H_ + grp * 32 + (col & 31);
            size_t base = (size_t)wrow * H_ + rank * KPB + kh * 128 + kc * 16;
            wreg[kc][ni][0] = f2h2(Whh[base + 2 * q],     Whh[base + 2 * q + 1]);
            wreg[kc][ni][1] = f2h2(Whh[base + 2 * q + 8], Whh[base + 2 * q + 9]);
        }

    for (int t = 0; t < T_SEQ; t++) {
        if (t > 0) {
            if (warp == 0 && lane < 8) {
                const unsigned tgt = 4u * (unsigned)t;
                const unsigned* cp = &g_cnt[rank * 8 + lane];
                unsigned v;
                do {
                    asm volatile("ld.acquire.gpu.u32 %0, [%1];" : "=r"(v) : "l"(cp) : "memory");
                } while (v < tgt);
            }
            __syncthreads();
        }

        const float* hsrc = (t == 0) ? h0 : g_hbuf[t % 3];

        // ---- stage h slice [64 x 256] -> fp16x2 SMEM ----
#pragma unroll
        for (int it = 0; it < 8; it++) {
            int id = tid + it * 256;
            int r = id >> 5, c8 = id & 31;
            const float* src = hsrc + (size_t)r * H_ + rank * KPB + c8 * 8;
            float4 v0 = __ldcg((const float4*)src);
            float4 v1 = __ldcg((const float4*)(src + 4));
            uint4 u = make_uint4(f2h2(v0.x, v0.y), f2h2(v0.z, v0.w),
                                 f2h2(v1.x, v1.y), f2h2(v1.z, v1.w));
            *(uint4*)&hs[r][c8 * 4] = u;
        }
        __syncthreads();

        // ---- prefetch gate inputs (fly during GEMM) ----
        float xr[2], xz[2], xn[2], hold[2];
#pragma unroll
        for (int o = 0; o < 2; o++) {
            const float* gxt = g_gx + ((size_t)t * B_ + b_o[o]) * G_;
            xr[o] = __ldcg(gxt + ghid_o[o]);
            xz[o] = __ldcg(gxt + H_ + ghid_o[o]);
            xn[o] = __ldcg(gxt + 2 * H_ + ghid_o[o]);
            hold[o] = (t == 0) ? h0[(size_t)b_o[o] * H_ + ghid_o[o]]
                               : __ldcg(&g_hbuf[t % 3][(size_t)b_o[o] * H_ + ghid_o[o]]);
        }

        // ---- GEMM: each warp 64Mx24Nx128K, fp16, B from registers ----
        float acc[4][3][4];
#pragma unroll
        for (int mi = 0; mi < 4; mi++)
#pragma unroll
            for (int ni = 0; ni < 3; ni++)
#pragma unroll
                for (int k = 0; k < 4; k++) acc[mi][ni][k] = 0.f;

#pragma unroll
        for (int kc = 0; kc < 8; kc++) {
            int kb2 = kh * 64 + kc * 8;
            unsigned a[4][4];
#pragma unroll
            for (int mi = 0; mi < 4; mi++) {
                int m0 = mi * 16 + g8;
                a[mi][0] = hs[m0][kb2 + q];
                a[mi][1] = hs[m0 + 8][kb2 + q];
                a[mi][2] = hs[m0][kb2 + q + 4];
                a[mi][3] = hs[m0 + 8][kb2 + q + 4];
            }
#pragma unroll
            for (int mi = 0; mi < 4; mi++)
#pragma unroll
                for (int ni = 0; ni < 3; ni++)
                    mma_f16(acc[mi][ni], a[mi], wreg[kc][ni]);
        }

        // W2: peers' DSMEM reads of previous step's ps done
        if (t > 0)
            asm volatile("barrier.cluster.wait.aligned;" ::: "memory");

        // epilogue: K-hi warps store ps, then K-lo warps accumulate
        if (kh == 1) {
#pragma unroll
            for (int mi = 0; mi < 4; mi++)
#pragma unroll
                for (int ni = 0; ni < 3; ni++) {
                    int n = wq * 24 + ni * 8 + 2 * q;
                    int m0 = mi * 16 + g8;
                    ps[m0][n] = acc[mi][ni][0];     ps[m0][n + 1] = acc[mi][ni][1];
                    ps[m0 + 8][n] = acc[mi][ni][2]; ps[m0 + 8][n + 1] = acc[mi][ni][3];
                }
        }
        __syncthreads();
        if (kh == 0) {
#pragma unroll
            for (int mi = 0; mi < 4; mi++)
#pragma unroll
                for (int ni = 0; ni < 3; ni++) {
                    int n = wq * 24 + ni * 8 + 2 * q;
                    int m0 = mi * 16 + g8;
                    ps[m0][n] += acc[mi][ni][0];     ps[m0][n + 1] += acc[mi][ni][1];
                    ps[m0 + 8][n] += acc[mi][ni][2]; ps[m0 + 8][n + 1] += acc[mi][ni][3];
                }
        }
        __syncthreads();

        // A1 + W1: all 4 ranks' ps visible
        asm volatile("barrier.cluster.arrive.aligned;" ::: "memory");
        asm volatile("barrier.cluster.wait.aligned;" ::: "memory");

        // ---- fused reduction + gates ----
        {
            float* hwr = g_hbuf[(t + 1) % 3];
#pragma unroll
            for (int o = 0; o < 2; o++) {
                float sr = 0.f, sz = 0.f, sn = 0.f;
#pragma unroll
                for (uint32_t r = 0; r < CLS; r++) {
                    uint32_t a0 = ps_base + (uint32_t)(b_o[o] * PT_W + uc_o[o]) * 4u;
                    sr += dsmem_ld(a0, r);
                    sz += dsmem_ld(a0 + 32 * 4, r);
                    sn += dsmem_ld(a0 + 64 * 4, r);
                }

                float rr = 1.f / (1.f + expf(-(xr[o] + sr + br_o[o])));
                float zz = 1.f / (1.f + expf(-(xz[o] + sz + bz_o[o])));
                float nn = tanhf(xn[o] + rr * (sn + bn_o[o]));
                float hv = (1.f - zz) * nn + zz * hold[o];

                hwr[(size_t)b_o[o] * H_ + ghid_o[o]] = hv;
                seqh[((size_t)t * B_ + b_o[o]) * H_ + ghid_o[o]] = __float2half_rn(hv);
                if (t == T_SEQ - 1)
                    hlast[(size_t)b_o[o] * H_ + ghid_o[o]] = hv;
            }
        }

        // A2: my DSMEM reads done (matched by W2 of t+1)
        asm volatile("barrier.cluster.arrive.aligned;" ::: "memory");

        __syncthreads();
        if (tid == 0)
            asm volatile("red.release.gpu.add.u32 [%0], %1;"
                         :: "l"(&g_cnt[grp]), "r"(1u) : "memory");
    }

    asm volatile("barrier.cluster.wait.aligned;" ::: "memory");
}

extern "C" void kernel_launch(void* const* d_in, const int* in_sizes, int n_in,
                              void* d_out, int out_size)
{
    const float* x   = (const float*)d_in[0];
    const float* h0  = (const float*)d_in[1];
    const float* Wih = (const float*)d_in[2];
    const float* Whh = (const float*)d_in[3];
    const float* bih = (const float*)d_in[4];
    const float* bhh = (const float*)d_in[5];
    float* out = (float*)d_out;

    cudaFuncSetAttribute(recur, cudaFuncAttributeMaxDynamicSharedMemorySize, SMEMB_R);
    cudaFuncSetAttribute(gx_gemm, cudaFuncAttributeMaxDynamicSharedMemorySize, GX_SMEM);

    // one-shot fp32 -> fp16 conversions
    {
        int n8x = (int)((size_t)T_SEQ * B_ * H_ / 8);
        int n8w = (int)((size_t)L_ * G_ * H_ / 8);
        tohalf<<<(n8x + 255) / 256, 256>>>(x, 0, n8x);
        tohalf<<<(n8w + 255) / 256, 256>>>(Wih, 1, n8w);
    }

    __half* wih_dev = nullptr;
    cudaGetSymbolAddress((void**)&wih_dev, g_wih);

    dim3 ggrid(G_ / 128, (T_SEQ * B_) / 128);
    for (int l = 0; l < L_; l++) {
        gx_gemm<<<ggrid, 256, GX_SMEM>>>(l == 0 ? 0 : (l == 1 ? 1 : 2),
                                         wih_dev + (size_t)l * G_ * H_,
                                         bih + (size_t)l * G_);
        reset_cnt<<<1, 32>>>();
        recur<<<NBLK, 256, SMEMB_R>>>(Whh + (size_t)l * G_ * H_,
                                      bhh + (size_t)l * G_,
                                      h0 + (size_t)l * B_ * H_,
                                      l & 1 ? 1 : 0,
                                      out + (size_t)l * B_ * H_);
    }
}

// round 15
// speedup vs baseline: 1.6231x; 1.0486x over previous
#include <cuda_runtime.h>
#include <cuda_fp16.h>
#include <cstdint>
#include <math.h>

#define T_SEQ 512
#define B_    64
#define H_    1024
#define G_    3072
#define L_    3
#define NBLK  128
#define CLS   4
#define NGRP  32
#define KPB   256

// recur dynamic SMEM (words): hs[64][132] fp16x2, ps[64][100] float
#define HS_W   132
#define PT_OFF (64 * HS_W)
#define PT_W   100
#define SMEMB_R ((PT_OFF + 64 * PT_W) * 4)   // 59392 B

// gx dynamic SMEM: A stages 2x(128x72) halfs, B stages 2x(128x72) halfs
#define GX_STG   9216
#define GX_SMEM  (4 * GX_STG * 2)             // 73728 B
#define GX_NK    16

__device__ float  g_gx[(size_t)T_SEQ * B_ * G_];
__device__ __half g_xh[(size_t)T_SEQ * B_ * H_];
__device__ __half g_wih[(size_t)L_ * G_ * H_];
__device__ __half g_h0h[(size_t)L_ * B_ * H_];
__device__ __half g_seqhA[(size_t)T_SEQ * B_ * H_];
__device__ __half g_seqhB[(size_t)T_SEQ * B_ * H_];
__device__ unsigned g_cnt[NGRP];

extern __shared__ unsigned sh[];

__device__ __forceinline__ unsigned f2h2(float lo, float hi) {
    __half2 h = __floats2half2_rn(lo, hi);
    return *(unsigned*)&h;
}

__device__ __forceinline__ void mma_f16(float* c, const unsigned* a, const unsigned* b) {
    asm volatile(
        "mma.sync.aligned.m16n8k16.row.col.f32.f16.f16.f32 "
        "{%0,%1,%2,%3}, {%4,%5,%6,%7}, {%8,%9}, {%0,%1,%2,%3};"
        : "+f"(c[0]), "+f"(c[1]), "+f"(c[2]), "+f"(c[3])
        : "r"(a[0]), "r"(a[1]), "r"(a[2]), "r"(a[3]), "r"(b[0]), "r"(b[1]));
}

__device__ __forceinline__ void ldsm4(unsigned* r, uint32_t addr) {
    asm volatile("ldmatrix.sync.aligned.m8n8.x4.shared.b16 {%0,%1,%2,%3}, [%4];"
                 : "=r"(r[0]), "=r"(r[1]), "=r"(r[2]), "=r"(r[3]) : "r"(addr));
}

__device__ __forceinline__ void cpa16(uint32_t dst, const void* src) {
    asm volatile("cp.async.cg.shared.global [%0], [%1], 16;" :: "r"(dst), "l"(src));
}

__global__ void reset_cnt() { if (threadIdx.x < NGRP) g_cnt[threadIdx.x] = 0u; }

// one-shot fp32 -> fp16 conversion (dstsel: 0 = g_xh, 1 = g_wih, 2 = g_h0h)
__global__ void tohalf(const float* __restrict__ s, int dstsel, int n8) {
    int i = blockIdx.x * 256 + threadIdx.x;
    if (i >= n8) return;
    __half* d = (dstsel == 0) ? g_xh : (dstsel == 1 ? g_wih : g_h0h);
    float4 a = *(const float4*)(s + (size_t)i * 8);
    float4 b = *(const float4*)(s + (size_t)i * 8 + 4);
    uint4 u = make_uint4(f2h2(a.x, a.y), f2h2(a.z, a.w), f2h2(b.x, b.y), f2h2(b.z, b.w));
    *(uint4*)(d + (size_t)i * 8) = u;
}

__device__ __forceinline__ uint32_t s2u(const void* p) {
    uint32_t a;
    asm("{ .reg .u64 t; cvta.to.shared.u64 t, %1; cvt.u32.u64 %0, t; }" : "=r"(a) : "l"(p));
    return a;
}

__device__ __forceinline__ float dsmem_ld(uint32_t laddr, uint32_t rank) {
    uint32_t ra; float v;
    asm("mapa.shared::cluster.u32 %0, %1, %2;" : "=r"(ra) : "r"(laddr), "r"(rank));
    asm volatile("ld.shared::cluster.f32 %0, [%1];" : "=f"(v) : "r"(ra) : "memory");
    return v;
}

// ---------------- input-gate GEMM: fp16 in, cp.async 2-stage, ldmatrix (unchanged) ----------------
__global__ void __launch_bounds__(256, 2) gx_gemm(int sel,
    const __half* __restrict__ Wbase, const float* __restrict__ bias)
{
    const __half* A = (sel == 0) ? g_xh : (sel == 1 ? g_seqhA : g_seqhB);
    const __half* W = Wbase;
    float* out = g_gx;

    const uint32_t smb = s2u(sh);
    const int tid = threadIdx.x, lane = tid & 31, warp = tid >> 5;
    const int mbase = blockIdx.y * 128, nbase = blockIdx.x * 128;
    const int wm = (warp >> 2) * 64;
    const int wn = (warp & 3) * 32;
    const int q = lane & 3, g8 = lane >> 2;

    const int a_off = (wm + (lane & 15)) * 144 + (lane >> 4) * 16;
    const int mm = lane >> 3;
    const int b_off = (wn + (mm >> 1) * 8 + (lane & 7)) * 144 + (mm & 1) * 16;

    int arow[4], aseg[4];
#pragma unroll
    for (int i = 0; i < 4; i++) {
        int id = tid + i * 256;
        arow[i] = id >> 3; aseg[i] = id & 7;
    }

    float acc[4][4][4];
#pragma unroll
    for (int i = 0; i < 4; i++)
#pragma unroll
        for (int j = 0; j < 4; j++)
#pragma unroll
            for (int k = 0; k < 4; k++) acc[i][j][k] = 0.f;

#define GX_STAGE(s, kt)                                                           \
    do {                                                                          \
        _Pragma("unroll")                                                         \
        for (int i = 0; i < 4; i++) {                                             \
            uint32_t dst = smb + ((s) * GX_STG + arow[i] * 72 + aseg[i] * 8) * 2; \
            cpa16(dst, A + (size_t)(mbase + arow[i]) * H_ + (kt) * 64 + aseg[i] * 8); \
        }                                                                         \
        _Pragma("unroll")                                                         \
        for (int i = 0; i < 4; i++) {                                             \
            uint32_t dst = smb + ((2 + (s)) * GX_STG + arow[i] * 72 + aseg[i] * 8) * 2; \
            cpa16(dst, W + (size_t)(nbase + arow[i]) * H_ + (kt) * 64 + aseg[i] * 8);  \
        }                                                                         \
        asm volatile("cp.async.commit_group;" ::: "memory");                      \
    } while (0)

    GX_STAGE(0, 0);

    for (int kt = 0; kt < GX_NK; kt++) {
        if (kt + 1 < GX_NK) {
            GX_STAGE((kt + 1) & 1, kt + 1);
            asm volatile("cp.async.wait_group 1;" ::: "memory");
        } else {
            asm volatile("cp.async.wait_group 0;" ::: "memory");
        }
        __syncthreads();

        const int s = kt & 1;
        const uint32_t abase = smb + s * GX_STG * 2 + a_off;
        const uint32_t bbase = smb + (2 + s) * GX_STG * 2 + b_off;
#pragma unroll
        for (int kc = 0; kc < 4; kc++) {
            unsigned a[4][4], b[2][4];
#pragma unroll
            for (int mi = 0; mi < 4; mi++)
                ldsm4(a[mi], abase + mi * 16 * 144 + kc * 32);
#pragma unroll
            for (int n2 = 0; n2 < 2; n2++)
                ldsm4(b[n2], bbase + n2 * 16 * 144 + kc * 32);
#pragma unroll
            for (int mi = 0; mi < 4; mi++)
#pragma unroll
                for (int ni = 0; ni < 4; ni++)
                    mma_f16(acc[mi][ni], a[mi], &b[ni >> 1][(ni & 1) * 2]);
        }
        __syncthreads();
    }

#pragma unroll
    for (int mi = 0; mi < 4; mi++) {
        int m = mbase + wm + mi * 16 + g8;
#pragma unroll
        for (int ni = 0; ni < 4; ni++) {
            int n = nbase + wn + ni * 8 + 2 * q;
            float b0 = bias[n], b1 = bias[n + 1];
            *(float2*)(out + (size_t)m * G_ + n) =
                make_float2(acc[mi][ni][0] + b0, acc[mi][ni][1] + b1);
            *(float2*)(out + (size_t)(m + 8) * G_ + n) =
                make_float2(acc[mi][ni][2] + b0, acc[mi][ni][3] + b1);
        }
    }
#undef GX_STAGE
}

// ---------------- persistent recurrence: cp.async fp16 staging, register hold ----------------
__global__ void __launch_bounds__(256, 1) __cluster_dims__(CLS, 1, 1) recur(
    const float* __restrict__ Whh, const float* __restrict__ bhh,
    const float* __restrict__ h0, const __half* __restrict__ h0h,
    int outsel, float* __restrict__ hlast, unsigned cbase)
{
    unsigned (*hs)[HS_W] = (unsigned(*)[HS_W])sh;
    float    (*ps)[PT_W] = (float(*)[PT_W])(sh + PT_OFF);
    __half* seqh = outsel ? g_seqhB : g_seqhA;

    const int tid = threadIdx.x, blk = blockIdx.x;
    const int grp = blk >> 2;
    const uint32_t rank = blk & 3;
    const int lane = tid & 31, warp = tid >> 5;
    const int q = lane & 3, g8 = lane >> 2;
    const int wq = warp & 3;
    const int kh = warp >> 2;

    const uint32_t hs_base = s2u(&hs[0][0]);
    const uint32_t ps_base = s2u(&ps[0][0]);

    // per-thread gate indices + loop-invariant biases + register hold state
    int b_o[2], ghid_o[2], uc_o[2];
    float br_o[2], bz_o[2], bn_o[2], hold[2];
#pragma unroll
    for (int o = 0; o < 2; o++) {
        int oi = tid + o * 256;
        b_o[o] = oi >> 3;
        uc_o[o] = (int)rank * 8 + (oi & 7);
        ghid_o[o] = grp * 32 + uc_o[o];
        br_o[o] = bhh[ghid_o[o]];
        bz_o[o] = bhh[H_ + ghid_o[o]];
        bn_o[o] = bhh[2 * H_ + ghid_o[o]];
        hold[o] = h0[(size_t)b_o[o] * H_ + ghid_o[o]];
    }

    // W_hh fragments in registers (fp16x2), once per layer
    unsigned wreg[8][3][2];
#pragma unroll
    for (int kc = 0; kc < 8; kc++)
#pragma unroll
        for (int ni = 0; ni < 3; ni++) {
            int col = wq * 24 + ni * 8 + g8;
            int wrow = (col >> 5) * H_ + grp * 32 + (col & 31);
            size_t base = (size_t)wrow * H_ + rank * KPB + kh * 128 + kc * 16;
            wreg[kc][ni][0] = f2h2(Whh[base + 2 * q],     Whh[base + 2 * q + 1]);
            wreg[kc][ni][1] = f2h2(Whh[base + 2 * q + 8], Whh[base + 2 * q + 9]);
        }

    for (int t = 0; t < T_SEQ; t++) {
        // ---- dataflow wait: my 8 producer groups finished step t-1 ----
        if (t > 0) {
            if (warp == 0 && lane < 8) {
                const unsigned tgt = cbase + 4u * (unsigned)t;
                const unsigned* cp = &g_cnt[rank * 8 + lane];
                unsigned v;
                do {
                    asm volatile("ld.acquire.gpu.u32 %0, [%1];" : "=r"(v) : "l"(cp) : "memory");
                } while (v < tgt);
            }
            __syncthreads();
        }

        // ---- stage h slice [64 x 256] fp16 via cp.async (no conversion) ----
        {
            const __half* hstage = (t == 0) ? h0h : (seqh + (size_t)(t - 1) * B_ * H_);
            const __half* src = hstage + rank * KPB;
#pragma unroll
            for (int i = 0; i < 8; i++) {
                int id = tid + i * 256;        // 0..2047 = 64 rows x 32 chunks(16B)
                int r = id >> 5, c16 = id & 31;
                uint32_t dst = hs_base + (uint32_t)(r * (HS_W * 4) + c16 * 16);
                cpa16(dst, src + (size_t)r * H_ + c16 * 8);
            }
            asm volatile("cp.async.commit_group;" ::: "memory");
            asm volatile("cp.async.wait_group 0;" ::: "memory");
        }
        __syncthreads();

        // ---- prefetch gate inputs (fly during GEMM) ----
        float xr[2], xz[2], xn[2];
#pragma unroll
        for (int o = 0; o < 2; o++) {
            const float* gxt = g_gx + ((size_t)t * B_ + b_o[o]) * G_;
            xr[o] = __ldcg(gxt + ghid_o[o]);
            xz[o] = __ldcg(gxt + H_ + ghid_o[o]);
            xn[o] = __ldcg(gxt + 2 * H_ + ghid_o[o]);
        }

        // ---- GEMM: each warp 64Mx24Nx128K, fp16, B from registers ----
        float acc[4][3][4];
#pragma unroll
        for (int mi = 0; mi < 4; mi++)
#pragma unroll
            for (int ni = 0; ni < 3; ni++)
#pragma unroll
                for (int k = 0; k < 4; k++) acc[mi][ni][k] = 0.f;

#pragma unroll
        for (int kc = 0; kc < 8; kc++) {
            int kb2 = kh * 64 + kc * 8;
            unsigned a[4][4];
#pragma unroll
            for (int mi = 0; mi < 4; mi++) {
                int m0 = mi * 16 + g8;
                a[mi][0] = hs[m0][kb2 + q];
                a[mi][1] = hs[m0 + 8][kb2 + q];
                a[mi][2] = hs[m0][kb2 + q + 4];
                a[mi][3] = hs[m0 + 8][kb2 + q + 4];
            }
#pragma unroll
            for (int mi = 0; mi < 4; mi++)
#pragma unroll
                for (int ni = 0; ni < 3; ni++)
                    mma_f16(acc[mi][ni], a[mi], wreg[kc][ni]);
        }

        // W2: peers' DSMEM reads of previous step's ps done
        if (t > 0)
            asm volatile("barrier.cluster.wait.aligned;" ::: "memory");

        // epilogue: K-hi warps store ps, then K-lo warps accumulate
        if (kh == 1) {
#pragma unroll
            for (int mi = 0; mi < 4; mi++)
#pragma unroll
                for (int ni = 0; ni < 3; ni++) {
                    int n = wq * 24 + ni * 8 + 2 * q;
                    int m0 = mi * 16 + g8;
                    ps[m0][n] = acc[mi][ni][0];     ps[m0][n + 1] = acc[mi][ni][1];
                    ps[m0 + 8][n] = acc[mi][ni][2]; ps[m0 + 8][n + 1] = acc[mi][ni][3];
                }
        }
        __syncthreads();
        if (kh == 0) {
#pragma unroll
            for (int mi = 0; mi < 4; mi++)
#pragma unroll
                for (int ni = 0; ni < 3; ni++) {
                    int n = wq * 24 + ni * 8 + 2 * q;
                    int m0 = mi * 16 + g8;
                    ps[m0][n] += acc[mi][ni][0];     ps[m0][n + 1] += acc[mi][ni][1];
                    ps[m0 + 8][n] += acc[mi][ni][2]; ps[m0 + 8][n + 1] += acc[mi][ni][3];
                }
        }
        __syncthreads();

        // A1 + W1: all 4 ranks' ps visible
        asm volatile("barrier.cluster.arrive.aligned;" ::: "memory");
        asm volatile("barrier.cluster.wait.aligned;" ::: "memory");

        // ---- fused reduction + gates ----
#pragma unroll
        for (int o = 0; o < 2; o++) {
            float sr = 0.f, sz = 0.f, sn = 0.f;
#pragma unroll
            for (uint32_t r = 0; r < CLS; r++) {
                uint32_t a0 = ps_base + (uint32_t)(b_o[o] * PT_W + uc_o[o]) * 4u;
                sr += dsmem_ld(a0, r);
                sz += dsmem_ld(a0 + 32 * 4, r);
                sn += dsmem_ld(a0 + 64 * 4, r);
            }

            float rr = 1.f / (1.f + expf(-(xr[o] + sr + br_o[o])));
            float zz = 1.f / (1.f + expf(-(xz[o] + sz + bz_o[o])));
            float nn = tanhf(xn[o] + rr * (sn + bn_o[o]));
            float hv = (1.f - zz) * nn + zz * hold[o];
            hold[o] = hv;

            seqh[((size_t)t * B_ + b_o[o]) * H_ + ghid_o[o]] = __float2half_rn(hv);
            if (t == T_SEQ - 1)
                hlast[(size_t)b_o[o] * H_ + ghid_o[o]] = hv;
        }

        // A2: my DSMEM reads done (matched by W2 of t+1)
        asm volatile("barrier.cluster.arrive.aligned;" ::: "memory");

        // publish: seqh writes for step t visible -> bump my group's counter
        __syncthreads();
        if (tid == 0)
            asm volatile("red.release.gpu.add.u32 [%0], %1;"
                         :: "l"(&g_cnt[grp]), "r"(1u) : "memory");
    }

    asm volatile("barrier.cluster.wait.aligned;" ::: "memory");
}

extern "C" void kernel_launch(void* const* d_in, const int* in_sizes, int n_in,
                              void* d_out, int out_size)
{
    const float* x   = (const float*)d_in[0];
    const float* h0  = (const float*)d_in[1];
    const float* Wih = (const float*)d_in[2];
    const float* Whh = (const float*)d_in[3];
    const float* bih = (const float*)d_in[4];
    const float* bhh = (const float*)d_in[5];
    float* out = (float*)d_out;

    cudaFuncSetAttribute(recur, cudaFuncAttributeMaxDynamicSharedMemorySize, SMEMB_R);
    cudaFuncSetAttribute(gx_gemm, cudaFuncAttributeMaxDynamicSharedMemorySize, GX_SMEM);

    // one-shot conversions + single counter reset (graph-replay safe)
    {
        int n8x = (int)((size_t)T_SEQ * B_ * H_ / 8);
        int n8w = (int)((size_t)L_ * G_ * H_ / 8);
        int n8h = (int)((size_t)L_ * B_ * H_ / 8);
        tohalf<<<(n8x + 255) / 256, 256>>>(x, 0, n8x);
        tohalf<<<(n8w + 255) / 256, 256>>>(Wih, 1, n8w);
        tohalf<<<(n8h + 255) / 256, 256>>>(h0, 2, n8h);
        reset_cnt<<<1, 32>>>();
    }

    __half* wih_dev = nullptr;
    __half* h0h_dev = nullptr;
    cudaGetSymbolAddress((void**)&wih_dev, g_wih);
    cudaGetSymbolAddress((void**)&h0h_dev, g_h0h);

    dim3 ggrid(G_ / 128, (T_SEQ * B_) / 128);
    for (int l = 0; l < L_; l++) {
        gx_gemm<<<ggrid, 256, GX_SMEM>>>(l == 0 ? 0 : (l == 1 ? 1 : 2),
                                         wih_dev + (size_t)l * G_ * H_,
                                         bih + (size_t)l * G_);
        recur<<<NBLK, 256, SMEMB_R>>>(Whh + (size_t)l * G_ * H_,
                                      bhh + (size_t)l * G_,
                                      h0 + (size_t)l * B_ * H_,
                                      h0h_dev + (size_t)l * B_ * H_,
                                      l & 1 ? 1 : 0,
                                      out + (size_t)l * B_ * H_,
                                      (unsigned)(l * 4 * T_SEQ));
    }
}